// round 12
// baseline (speedup 1.0000x reference)
#include <cuda_runtime.h>
#include <cuda_bf16.h>
#include <math.h>
#include <stdint.h>

#define D 512
#define T 2048
#define NBATCH 32
#define NB 512
#define R (NBATCH*T)          // 65536 rows
#define M_TILE 64
#define CTAS (R/M_TILE)       // 1024

// -------- scratch (__device__ globals; no allocations allowed) --------
__device__ __align__(16) char g_Cbq[NB*D];   // codebook int8 (K-major)
__device__ float g_cnorm[NB];
__device__ float g_cs[NB];                   // per-code dequant scale = max|c|/127
__device__ int   g_hist[NB];
__device__ float g_blockCommit[CTAS];

// -------- helpers --------
__device__ __forceinline__ uint32_t smem_u32(const void* p){
    uint32_t a;
    asm("{ .reg .u64 t; cvta.to.shared.u64 t, %1; cvt.u32.u64 %0, t; }" : "=r"(a) : "l"(p));
    return a;
}
__device__ __forceinline__ void ldsm4(uint32_t (&r)[4], uint32_t addr){
    asm volatile("ldmatrix.sync.aligned.m8n8.x4.shared.b16 {%0,%1,%2,%3}, [%4];"
        : "=r"(r[0]), "=r"(r[1]), "=r"(r[2]), "=r"(r[3]) : "r"(addr));
}
__device__ __forceinline__ void mma_s8(int (&c)[4], const uint32_t (&a)[4],
                                       uint32_t b0, uint32_t b1){
    asm volatile("mma.sync.aligned.m16n8k32.row.col.s32.s8.s8.s32 "
        "{%0,%1,%2,%3}, {%4,%5,%6,%7}, {%8,%9}, {%0,%1,%2,%3};"
        : "+r"(c[0]), "+r"(c[1]), "+r"(c[2]), "+r"(c[3])
        : "r"(a[0]), "r"(a[1]), "r"(a[2]), "r"(a[3]), "r"(b0), "r"(b1));
}
__device__ __forceinline__ void cpasync16(uint32_t dst, const void* src){
    asm volatile("cp.async.cg.shared.global [%0], [%1], 16;" :: "r"(dst), "l"(src) : "memory");
}
#define CP_COMMIT() asm volatile("cp.async.commit_group;" ::: "memory")
#define CP_WAIT1()  asm volatile("cp.async.wait_group 1;" ::: "memory")

// ---------------- prep: codebook -> int8 + scales, cnorm, zero hist ----------------
__global__ void prep_cb(const float* __restrict__ codebook) {
    int c = blockIdx.x, d = threadIdx.x;
    float v = codebook[c*D + d];
    __shared__ float sbuf[D];
    __shared__ float mbuf[D];
    sbuf[d] = v*v;
    mbuf[d] = fabsf(v);
    __syncthreads();
    for (int s = 256; s > 0; s >>= 1) {
        if (d < s) { sbuf[d] += sbuf[d+s]; mbuf[d] = fmaxf(mbuf[d], mbuf[d+s]); }
        __syncthreads();
    }
    float mx = fmaxf(mbuf[0], 1e-30f);
    float sx = 127.0f / mx;
    g_Cbq[c*D + d] = (char)__float2int_rn(v * sx);
    if (d == 0) {
        g_cnorm[c] = sbuf[0];
        g_cs[c]    = mx / 127.0f;
        g_hist[c]  = 0;
    }
}

// ---------------- fused main ----------------
// smem layout
#define SM_CN    0          // 2048
#define SM_CS    2048       // 2048
#define SM_INV   4096       // 256
#define SM_SQ    4352       // 256
#define SM_CM    4608       // 256
#define SM_IDX   4864       // 256
#define SM_FXR   5120       // 256  (-2*inv*maxx/127 per row)
#define SM_IDX4  5376       // 1024
#define SM_FLAG  6400       // 256
#define SM_PROVS 6656       // 256
#define SM_PROVI 6912       // 256
#define SM_AFULL 8192       // 32 KB: 4 chunks x [64m][128 k-int8] swizzled
#define SM_BST   (8192 + 32768)     // 40960
#define B_STAGE  16384      // 128 codes x 128 k-int8
#define SMEM_TOTAL (SM_BST + 2*B_STAGE)   // 73728
// post-loop overlays on B stage 0
#define OV_REDS  SM_BST             // float[64*16] = 4KB
#define OV_REDI  (SM_BST + 4096)    // int[64*16]   = 4KB

__global__ __launch_bounds__(256, 2) void vq_main(const float* __restrict__ x,
                                                  const float* __restrict__ codebook,
                                                  float* __restrict__ out) {
    extern __shared__ char smem[];
    const uint32_t sb = smem_u32(smem);
    float* cn_s  = reinterpret_cast<float*>(smem + SM_CN);
    float* cs_s  = reinterpret_cast<float*>(smem + SM_CS);
    float* inv_s = reinterpret_cast<float*>(smem + SM_INV);
    float* sq_s  = reinterpret_cast<float*>(smem + SM_SQ);
    float* cm_s  = reinterpret_cast<float*>(smem + SM_CM);
    int*   idx_s = reinterpret_cast<int*>(smem + SM_IDX);
    float* fxr_s = reinterpret_cast<float*>(smem + SM_FXR);
    int*   idx4_s= reinterpret_cast<int*>(smem + SM_IDX4);
    int*   flag_s= reinterpret_cast<int*>(smem + SM_FLAG);
    float* provS = reinterpret_cast<float*>(smem + SM_PROVS);
    int*   provI = reinterpret_cast<int*>(smem + SM_PROVI);
    float* red_s = reinterpret_cast<float*>(smem + OV_REDS);
    int*   red_i = reinterpret_cast<int*>(smem + OV_REDI);

    const int tid  = threadIdx.x;
    const int lane = tid & 31, wid = tid >> 5;
    const int wm = wid & 3, wn = wid >> 2;        // 4 x 2 warp grid, warp tile 16x64
    const int blk  = blockIdx.x;
    const int row0 = blk * M_TILE;
    const int n    = row0 / T;
    const int t0   = row0 % T;

    for (int i = tid; i < NB; i += 256) { cn_s[i] = g_cnorm[i]; cs_s[i] = g_cs[i]; }

    // B chunk prefetch: 128 codes x 128 k-int8 (16KB) into stage stg
    auto prefetchB = [&](int c, int stg){
        const int kc = c & 3;
        const int n0 = (c >> 2) * 128;
        uint32_t base = sb + SM_BST + stg*B_STAGE;
        #pragma unroll
        for (int t2 = 0; t2 < 4; ++t2) {
            int i = tid + t2*256;
            int r = i >> 3, q = i & 7;
            uint32_t off = (uint32_t)(r*128) + (((uint32_t)q*16) ^ (((uint32_t)(r & 7))*16));
            cpasync16(base + off, g_Cbq + (size_t)(n0 + r)*D + kc*128 + q*16);
        }
    };

    prefetchB(0, 0); CP_COMMIT();
    prefetchB(1, 1); CP_COMMIT();

    // ---- A prologue (two-pass): exact row max + sumsq, then int8 quantize ----
    {
        const int m  = tid >> 2;   // t-row within tile
        const int sg = tid & 3;    // k-chunk of 128
        const float* xc = x + ((size_t)n*D + sg*128)*T + t0 + m;
        float mx = 0.f, ss = 0.f;
        #pragma unroll 8
        for (int j = 0; j < 128; ++j) {
            float v = xc[(size_t)j*T];
            ss = fmaf(v, v, ss);
            mx = fmaxf(mx, fabsf(v));
        }
        // exact quad reductions (deterministic: max exact, adds commutative)
        mx = fmaxf(mx, __shfl_xor_sync(0xffffffffu, mx, 1));
        mx = fmaxf(mx, __shfl_xor_sync(0xffffffffu, mx, 2));
        ss += __shfl_xor_sync(0xffffffffu, ss, 1);
        ss += __shfl_xor_sync(0xffffffffu, ss, 2);
        mx = fmaxf(mx, 1e-30f);
        const float sx = 127.0f / mx;
        if (sg == 0) {
            sq_s[m]  = ss;
            float inv = 1.0f / fmaxf(sqrtf(ss), 1e-12f);
            inv_s[m] = inv;
            fxr_s[m] = -2.0f * inv * mx / 127.0f;   // = -2*inv/sx
        }
        // pass 2: reload (L2-hot) and quantize into swizzled A-full chunk sg
        char* arow = smem + SM_AFULL + sg*8192 + m*128;
        #pragma unroll
        for (int j8 = 0; j8 < 8; ++j8) {
            float v[16];
            #pragma unroll
            for (int e = 0; e < 16; ++e) v[e] = xc[(size_t)(j8*16 + e)*T];
            uint32_t pk[4];
            #pragma unroll
            for (int w = 0; w < 4; ++w) {
                uint32_t b0 = (uint32_t)(uint8_t)(char)__float2int_rn(v[4*w+0]*sx);
                uint32_t b1 = (uint32_t)(uint8_t)(char)__float2int_rn(v[4*w+1]*sx);
                uint32_t b2 = (uint32_t)(uint8_t)(char)__float2int_rn(v[4*w+2]*sx);
                uint32_t b3 = (uint32_t)(uint8_t)(char)__float2int_rn(v[4*w+3]*sx);
                pk[w] = b0 | (b1 << 8) | (b2 << 16) | (b3 << 24);
            }
            int seg = j8 ^ (m & 7);
            *reinterpret_cast<uint4*>(arow + seg*16) = make_uint4(pk[0], pk[1], pk[2], pk[3]);
        }
    }
    __syncthreads();

    // per-slot running top-2 (2 row-slots per thread)
    float bs1[2], bs2[2]; int bi1[2], bi2[2];
    #pragma unroll
    for (int s = 0; s < 2; ++s) { bs1[s] = 3.4e38f; bs2[s] = 3.4e38f; bi1[s] = 0; bi2[s] = 0; }

    int acc[8][4];
    #pragma unroll
    for (int b = 0; b < 8; ++b)
        #pragma unroll
        for (int e = 0; e < 4; ++e) acc[b][e] = 0;

    // fragment address bases (byte-identical to proven bf16 math)
    const int rA = wm*16 + (lane & 7) + ((lane >> 3) & 1)*8;
    const uint32_t rowA = (uint32_t)rA * 128;
    const uint32_t kxA  = ((uint32_t)(lane >> 4)) * 16;
    const uint32_t swA  = ((uint32_t)(rA & 7)) * 16;
    const int rBl = (lane & 7) + (lane >> 4)*8;
    const uint32_t kxB  = (((uint32_t)(lane >> 3)) & 1) * 16;
    const uint32_t swB  = ((uint32_t)(lane & 7)) * 16;
    const uint32_t rowB = (uint32_t)(wn*64 + rBl) * 128;

    // ---- mainloop: 4 passes x 4 k-chunks (k128 int8), B double-buffered ----
    for (int c = 0; c < 16; ++c) {
        const int kc = c & 3;
        CP_WAIT1();                    // my group c complete
        __syncthreads();               // all threads' group c complete
        uint32_t bb = sb + SM_BST + (c & 1)*B_STAGE;
        uint32_t aBase = sb + SM_AFULL + kc*8192;

        #pragma unroll
        for (int ks = 0; ks < 4; ++ks) {
            uint32_t bh[4][4];
            #pragma unroll
            for (int nt2 = 0; nt2 < 4; ++nt2)
                ldsm4(bh[nt2], bb + rowB + (uint32_t)nt2*2048 + (((uint32_t)ks*32 + kxB) ^ swB));
            uint32_t aa[4];
            ldsm4(aa, aBase + rowA + (((uint32_t)ks*32 + kxA) ^ swA));
            #pragma unroll
            for (int nt2 = 0; nt2 < 4; ++nt2) {
                mma_s8(acc[2*nt2],   aa, bh[nt2][0], bh[nt2][1]);
                mma_s8(acc[2*nt2+1], aa, bh[nt2][2], bh[nt2][3]);
            }
        }

        if (kc == 3) {   // end of pass: fold 128 codes into running top-2
            const int n0 = (c >> 2) * 128;
            #pragma unroll
            for (int h = 0; h < 2; ++h) {
                const int row = wm*16 + (lane >> 2) + h*8;
                const float fx = fxr_s[row];
                #pragma unroll
                for (int nt = 0; nt < 8; ++nt) {
                    int code = n0 + wn*64 + nt*8 + (lane & 3)*2;
                    float s0 = fmaf(fx*cs_s[code],   (float)acc[nt][h*2+0], cn_s[code]);
                    float s1 = fmaf(fx*cs_s[code+1], (float)acc[nt][h*2+1], cn_s[code+1]);
                    if (s0 < bs1[h]) { bs2[h]=bs1[h]; bi2[h]=bi1[h]; bs1[h]=s0; bi1[h]=code; }
                    else if (s0 < bs2[h]) { bs2[h]=s0; bi2[h]=code; }
                    if (s1 < bs1[h]) { bs2[h]=bs1[h]; bi2[h]=bi1[h]; bs1[h]=s1; bi1[h]=code+1; }
                    else if (s1 < bs2[h]) { bs2[h]=s1; bi2[h]=code+1; }
                }
            }
            #pragma unroll
            for (int b = 0; b < 8; ++b)
                #pragma unroll
                for (int e = 0; e < 4; ++e) acc[b][e] = 0;
        }

        __syncthreads();               // readers of stage c&1 done before overwrite
        if (c + 2 < 16) { prefetchB(c + 2, c & 1); }
        CP_COMMIT();
    }

    // ---- candidate reduction: 8 slices x top-2 = 16 candidates/row ----
    __syncthreads();
    #pragma unroll
    for (int h = 0; h < 2; ++h) {
        const int row = wm*16 + (lane >> 2) + h*8;
        const int cb = (wn*4 + (lane & 3))*2;
        red_s[row*16 + cb]     = bs1[h]; red_i[row*16 + cb]     = bi1[h];
        red_s[row*16 + cb + 1] = bs2[h]; red_i[row*16 + cb + 1] = bi2[h];
    }
    __syncthreads();

    if (tid < M_TILE) {
        float s1 = 3.4e38f, s2 = s1, s3 = s1, s4 = s1;
        int i1 = 0, i2 = 0, i3 = 0, i4 = 0;
        #pragma unroll
        for (int c = 0; c < 16; ++c) {
            float s = red_s[tid*16 + c]; int ii = red_i[tid*16 + c];
            if (s < s1 || (s == s1 && ii < i1)) { s4=s3;i4=i3; s3=s2;i3=i2; s2=s1;i2=i1; s1=s;i1=ii; }
            else if (s < s2 || (s == s2 && ii < i2)) { s4=s3;i4=i3; s3=s2;i3=i2; s2=s;i2=ii; }
            else if (s < s3 || (s == s3 && ii < i3)) { s4=s3;i4=i3; s3=s;i3=ii; }
            else if (s < s4 || (s == s4 && ii < i4)) { s4=s;i4=ii; }
        }
        idx4_s[tid*4+0] = i1; idx4_s[tid*4+1] = i2;
        idx4_s[tid*4+2] = i3; idx4_s[tid*4+3] = i4;
        flag_s[tid] = (s2 - s1 < 1.2e-2f) ? 1 : 0;   // 11-sigma of int8 quant noise
        provS[tid] = s1; provI[tid] = i1;
    }
    __syncthreads();

    // ---- quad-cooperative exact-fp32 rescue: 4 same-warp threads per row ----
    {
        const int row = tid >> 2, part = tid & 3;
        const int flg = flag_s[row];
        float p0 = 0.f, p1 = 0.f, p2 = 0.f, p3 = 0.f;
        int ic0 = idx4_s[row*4+0], ic1 = idx4_s[row*4+1];
        int ic2 = idx4_s[row*4+2], ic3 = idx4_s[row*4+3];
        if (flg) {
            const float* xr = x + (size_t)n*D*T + t0 + row;
            const float* cb0 = codebook + (size_t)ic0*D;
            const float* cb1 = codebook + (size_t)ic1*D;
            const float* cb2 = codebook + (size_t)ic2*D;
            const float* cb3 = codebook + (size_t)ic3*D;
            const int dlo = part*128;
            #pragma unroll 4
            for (int d = dlo; d < dlo + 128; ++d) {
                float xv = xr[(size_t)d*T];
                p0 = fmaf(xv, cb0[d], p0);
                p1 = fmaf(xv, cb1[d], p1);
                p2 = fmaf(xv, cb2[d], p2);
                p3 = fmaf(xv, cb3[d], p3);
            }
        }
        p0 += __shfl_xor_sync(0xffffffffu, p0, 1);
        p1 += __shfl_xor_sync(0xffffffffu, p1, 1);
        p2 += __shfl_xor_sync(0xffffffffu, p2, 1);
        p3 += __shfl_xor_sync(0xffffffffu, p3, 1);
        p0 += __shfl_xor_sync(0xffffffffu, p0, 2);
        p1 += __shfl_xor_sync(0xffffffffu, p1, 2);
        p2 += __shfl_xor_sync(0xffffffffu, p2, 2);
        p3 += __shfl_xor_sync(0xffffffffu, p3, 2);
        if (part == 0) {
            float bestS = provS[row]; int bestI = provI[row];
            if (flg) {
                const float inv = inv_s[row];
                float e0 = fmaf(-2.0f*inv, p0, cn_s[ic0]);
                float e1 = fmaf(-2.0f*inv, p1, cn_s[ic1]);
                float e2 = fmaf(-2.0f*inv, p2, cn_s[ic2]);
                float e3 = fmaf(-2.0f*inv, p3, cn_s[ic3]);
                bestS = e0; bestI = ic0;
                if (e1 < bestS || (e1 == bestS && ic1 < bestI)) { bestS = e1; bestI = ic1; }
                if (e2 < bestS || (e2 == bestS && ic2 < bestI)) { bestS = e2; bestI = ic2; }
                if (e3 < bestS || (e3 == bestS && ic3 < bestI)) { bestS = e3; bestI = ic3; }
            }
            idx_s[row] = bestI;
            cm_s[row] = fmaf(sq_s[row]*inv_s[row], inv_s[row], bestS);
            atomicAdd(&g_hist[bestI], 1);
        }
    }
    __syncthreads();
    if (tid == 0) {
        float s = 0.f;
        for (int i = 0; i < M_TILE; ++i) s += cm_s[i];
        g_blockCommit[blk] = s;
    }

    // ---- fused output: gather + register transpose + coalesced write ----
    {
        const int mq = tid & 15;      // t-quad
        const int dg = tid >> 4;      // d-group of 4
        int r0i = idx_s[4*mq + 0], r1i = idx_s[4*mq + 1];
        int r2i = idx_s[4*mq + 2], r3i = idx_s[4*mq + 3];
        #pragma unroll
        for (int dt = 0; dt < 8; ++dt) {
            const int d0 = dt*64 + dg*4;
            float4 a = *reinterpret_cast<const float4*>(codebook + (size_t)r0i*D + d0);
            float4 b = *reinterpret_cast<const float4*>(codebook + (size_t)r1i*D + d0);
            float4 cc = *reinterpret_cast<const float4*>(codebook + (size_t)r2i*D + d0);
            float4 dd = *reinterpret_cast<const float4*>(codebook + (size_t)r3i*D + d0);
            float* ob = out + ((size_t)n*D + d0)*T + t0 + 4*mq;
            *reinterpret_cast<float4*>(ob)              = make_float4(a.x, b.x, cc.x, dd.x);
            *reinterpret_cast<float4*>(ob + T)          = make_float4(a.y, b.y, cc.y, dd.y);
            *reinterpret_cast<float4*>(ob + 2*(size_t)T)= make_float4(a.z, b.z, cc.z, dd.z);
            *reinterpret_cast<float4*>(ob + 3*(size_t)T)= make_float4(a.w, b.w, cc.w, dd.w);
        }
    }
}

// ---------------- finalize: perplexity + commit mean ----------------
__global__ void finalize_kernel(float* __restrict__ out) {
    __shared__ double sbuf[512];
    int t = threadIdx.x;
    float prob = (float)g_hist[t] / 65536.0f;
    sbuf[t] = (double)(prob * logf(prob + 1e-7f));
    __syncthreads();
    for (int s = 256; s > 0; s >>= 1) { if (t < s) sbuf[t] += sbuf[t+s]; __syncthreads(); }
    double psum = sbuf[0];
    __syncthreads();
    double c = 0.0;
    for (int i = t; i < CTAS; i += 512) c += (double)g_blockCommit[i];
    sbuf[t] = c;
    __syncthreads();
    for (int s = 256; s > 0; s >>= 1) { if (t < s) sbuf[t] += sbuf[t+s]; __syncthreads(); }
    if (t == 0) {
        out[(size_t)R*D]     = (float)(sbuf[0] / ((double)R * (double)D));
        out[(size_t)R*D + 1] = expf((float)(-psum));
    }
}

// ---------------- launch ----------------
extern "C" void kernel_launch(void* const* d_in, const int* in_sizes, int n_in,
                              void* d_out, int out_size) {
    const float* x        = (const float*)d_in[0];
    const float* codebook = (const float*)d_in[1];
    float* out = (float*)d_out;

    cudaFuncSetAttribute(vq_main, cudaFuncAttributeMaxDynamicSharedMemorySize, SMEM_TOTAL);

    prep_cb<<<NB, D>>>(codebook);
    vq_main<<<CTAS, 256, SMEM_TOTAL>>>(x, codebook, out);
    finalize_kernel<<<1, 512>>>(out);
}

// round 13
// speedup vs baseline: 1.5462x; 1.5462x over previous
#include <cuda_runtime.h>
#include <cuda_bf16.h>
#include <math.h>
#include <stdint.h>

#define D 512
#define T 2048
#define NBATCH 32
#define NB 512
#define R (NBATCH*T)          // 65536 rows
#define M_TILE 64
#define CTAS (R/M_TILE)       // 1024

// -------- scratch (__device__ globals; no allocations allowed) --------
__device__ __align__(16) __nv_bfloat16 g_Cbh[NB*D];         // codebook bf16 (K-major)
__device__ float g_cnorm[NB];
__device__ int   g_hist[NB];
__device__ float g_blockCommit[CTAS];

// -------- helpers --------
__device__ __forceinline__ uint32_t smem_u32(const void* p){
    uint32_t a;
    asm("{ .reg .u64 t; cvta.to.shared.u64 t, %1; cvt.u32.u64 %0, t; }" : "=r"(a) : "l"(p));
    return a;
}
__device__ __forceinline__ void ldsm4(uint32_t (&r)[4], uint32_t addr){
    asm volatile("ldmatrix.sync.aligned.m8n8.x4.shared.b16 {%0,%1,%2,%3}, [%4];"
        : "=r"(r[0]), "=r"(r[1]), "=r"(r[2]), "=r"(r[3]) : "r"(addr));
}
__device__ __forceinline__ void mma_bf16(float (&c)[4], const uint32_t (&a)[4],
                                         uint32_t b0, uint32_t b1){
    asm volatile("mma.sync.aligned.m16n8k16.row.col.f32.bf16.bf16.f32 "
        "{%0,%1,%2,%3}, {%4,%5,%6,%7}, {%8,%9}, {%0,%1,%2,%3};"
        : "+f"(c[0]), "+f"(c[1]), "+f"(c[2]), "+f"(c[3])
        : "r"(a[0]), "r"(a[1]), "r"(a[2]), "r"(a[3]), "r"(b0), "r"(b1));
}
__device__ __forceinline__ void cpasync16(uint32_t dst, const void* src){
    asm volatile("cp.async.cg.shared.global [%0], [%1], 16;" :: "r"(dst), "l"(src) : "memory");
}
#define CP_COMMIT() asm volatile("cp.async.commit_group;" ::: "memory")
#define CP_WAIT1()  asm volatile("cp.async.wait_group 1;" ::: "memory")

// ---------------- prep: codebook -> bf16, cnorm, zero hist ----------------
__global__ void prep_cb(const float* __restrict__ codebook) {
    int c = blockIdx.x, d = threadIdx.x;
    float v = codebook[c*D + d];
    g_Cbh[c*D + d] = __float2bfloat16_rn(v);
    __shared__ float sbuf[D];
    sbuf[d] = v*v;
    __syncthreads();
    for (int s = 256; s > 0; s >>= 1) {
        if (d < s) sbuf[d] += sbuf[d+s];
        __syncthreads();
    }
    if (d == 0) { g_cnorm[c] = sbuf[0]; g_hist[c] = 0; }
}

// ---------------- fused main ----------------
// smem layout (resident)
#define SM_INV   0          // 256
#define SM_SQ    256        // 256
#define SM_AFULL 1024       // 64 KB: 8 chunks x [64m][64k] bf16 swizzled
#define SM_BST   (1024 + 65536)     // 66560
#define B_STAGE  16384      // 128 codes x 64k bf16
#define NSTAGE   3
#define SMEM_TOTAL (SM_BST + NSTAGE*B_STAGE)   // 115712 (113 KiB -> 2 CTA/SM)
// prologue overlay (stage 2 untouched until chunk 0)
#define OV_PART  (SM_BST + 2*B_STAGE)   // float[4*64]
// post-loop overlays (stages 0/1)
#define OV_REDS  SM_BST             // float[64*16]
#define OV_REDI  (SM_BST + 4096)    // int[64*16]
#define OV_IDX4  (SM_BST + 8192)    // int[64*4]
#define OV_FLAG  (SM_BST + 9216)    // int[64]
#define OV_PROVS (SM_BST + 9472)    // float[64]
#define OV_PROVI (SM_BST + 9728)    // int[64]
#define OV_CM    (SM_BST + 9984)    // float[64]
#define OV_IDX   (SM_BST + 10240)   // int[64]

__global__ __launch_bounds__(256, 2) void vq_main(const float* __restrict__ x,
                                                  const float* __restrict__ codebook,
                                                  float* __restrict__ out) {
    extern __shared__ char smem[];
    const uint32_t sb = smem_u32(smem);
    float* inv_s = reinterpret_cast<float*>(smem + SM_INV);
    float* sq_s  = reinterpret_cast<float*>(smem + SM_SQ);
    float* part_s= reinterpret_cast<float*>(smem + OV_PART);
    float* red_s = reinterpret_cast<float*>(smem + OV_REDS);
    int*   red_i = reinterpret_cast<int*>(smem + OV_REDI);
    int*   idx4_s= reinterpret_cast<int*>(smem + OV_IDX4);
    int*   flag_s= reinterpret_cast<int*>(smem + OV_FLAG);
    float* provS = reinterpret_cast<float*>(smem + OV_PROVS);
    int*   provI = reinterpret_cast<int*>(smem + OV_PROVI);
    float* cm_s  = reinterpret_cast<float*>(smem + OV_CM);
    int*   idx_s = reinterpret_cast<int*>(smem + OV_IDX);

    const int tid  = threadIdx.x;
    const int lane = tid & 31, wid = tid >> 5;
    const int wm = wid & 3, wn = wid >> 2;        // 4 x 2 warp grid, warp tile 16x64
    const int blk  = blockIdx.x;
    const int row0 = blk * M_TILE;
    const int n    = row0 / T;
    const int t0   = row0 % T;

    // B chunk prefetch: 128 codes x 64 k bf16 (16KB) into stage stg
    auto prefetchB = [&](int c, int stg){
        const int kc = c & 7;
        const int n0 = (c >> 3) * 128;
        uint32_t base = sb + SM_BST + stg*B_STAGE;
        #pragma unroll
        for (int t2 = 0; t2 < 4; ++t2) {
            int i = tid + t2*256;
            int r = i >> 3, q = i & 7;
            uint32_t off = (uint32_t)(r*128) + (((uint32_t)q*16) ^ (((uint32_t)(r & 7))*16));
            cpasync16(base + off, g_Cbh + (size_t)(n0 + r)*D + kc*64 + q*8);
        }
    };

    prefetchB(0, 0); CP_COMMIT();
    prefetchB(1, 1); CP_COMMIT();

    // ---- A prologue: LDG x slice, convert bf16, store swizzled A-full; sumsq ----
    {
        const int m  = tid >> 2;   // t-row within tile
        const int sg = tid & 3;    // k-subgroup of 16
        float ss = 0.f;
        for (int kc = 0; kc < 8; ++kc) {
            const float* xc = x + ((size_t)n*D + kc*64 + 16*sg)*T + t0 + m;
            float v[16];
            #pragma unroll
            for (int j = 0; j < 16; ++j) v[j] = xc[(size_t)j*T];
            #pragma unroll
            for (int j = 0; j < 16; ++j) ss = fmaf(v[j], v[j], ss);
            uint32_t pk[8];
            #pragma unroll
            for (int jp = 0; jp < 8; ++jp) {
                __nv_bfloat16 a = __float2bfloat16_rn(v[2*jp]);
                __nv_bfloat16 b = __float2bfloat16_rn(v[2*jp+1]);
                pk[jp] = (uint32_t)__bfloat16_as_ushort(a) | ((uint32_t)__bfloat16_as_ushort(b) << 16);
            }
            char* arow = smem + SM_AFULL + kc*8192 + m*128;
            int seg0 = (2*sg) ^ (m & 7);
            int seg1 = (2*sg+1) ^ (m & 7);
            *reinterpret_cast<uint4*>(arow + seg0*16) = make_uint4(pk[0], pk[1], pk[2], pk[3]);
            *reinterpret_cast<uint4*>(arow + seg1*16) = make_uint4(pk[4], pk[5], pk[6], pk[7]);
        }
        part_s[sg*64 + m] = ss;
    }
    __syncthreads();
    if (tid < M_TILE) {   // fixed-order combine -> deterministic
        float sq = part_s[tid] + part_s[64+tid] + part_s[128+tid] + part_s[192+tid];
        sq_s[tid]  = sq;
        inv_s[tid] = 1.0f / fmaxf(sqrtf(sq), 1e-12f);
    }

    // per-slot running top-2 (2 row-slots per thread)
    float bs1[2], bs2[2]; int bi1[2], bi2[2];
    #pragma unroll
    for (int s = 0; s < 2; ++s) { bs1[s] = 3.4e38f; bs2[s] = 3.4e38f; bi1[s] = 0; bi2[s] = 0; }

    float acc[8][4];
    #pragma unroll
    for (int b = 0; b < 8; ++b)
        #pragma unroll
        for (int e = 0; e < 4; ++e) acc[b][e] = 0.f;

    // fragment address bases (proven R9 math)
    const int rA = wm*16 + (lane & 7) + ((lane >> 3) & 1)*8;
    const uint32_t rowA = (uint32_t)rA * 128;
    const uint32_t kxA  = ((uint32_t)(lane >> 4)) * 16;
    const uint32_t swA  = ((uint32_t)(rA & 7)) * 16;
    const int rBl = (lane & 7) + (lane >> 4)*8;
    const uint32_t kxB  = (((uint32_t)(lane >> 3)) & 1) * 16;
    const uint32_t swB  = ((uint32_t)(lane & 7)) * 16;
    const uint32_t rowB = (uint32_t)(wn*64 + rBl) * 128;

    // ---- mainloop: 4 passes x 8 k-chunks, 3-stage B, ONE sync per chunk ----
    for (int c = 0; c < 32; ++c) {
        const int kc = c & 7;
        const uint32_t aBase = sb + SM_AFULL + kc*8192;

        // A-frag preload: resident smem, independent of cp.async/barrier
        uint32_t aa[4][4];
        #pragma unroll
        for (int ks = 0; ks < 4; ++ks)
            ldsm4(aa[ks], aBase + rowA + (((uint32_t)ks*32 + kxA) ^ swA));

        CP_WAIT1();                    // my group c complete (group c+1 may be pending)
        __syncthreads();               // all threads: group c visible AND chunk c-1 reads done
        if (c + 2 < 32) { prefetchB(c + 2, (c + 2) % NSTAGE); }   // target stage read at c-1
        CP_COMMIT();

        uint32_t bb = sb + SM_BST + (c % NSTAGE)*B_STAGE;
        #pragma unroll
        for (int ks = 0; ks < 4; ++ks) {
            uint32_t bh[4][4];
            #pragma unroll
            for (int nt2 = 0; nt2 < 4; ++nt2)
                ldsm4(bh[nt2], bb + rowB + (uint32_t)nt2*2048 + (((uint32_t)ks*32 + kxB) ^ swB));
            #pragma unroll
            for (int nt2 = 0; nt2 < 4; ++nt2) {
                mma_bf16(acc[2*nt2],   aa[ks], bh[nt2][0], bh[nt2][1]);
                mma_bf16(acc[2*nt2+1], aa[ks], bh[nt2][2], bh[nt2][3]);
            }
        }

        if (kc == 7) {   // end of pass: fold 128 codes into running top-2
            const int n0 = (c >> 3) * 128;
            #pragma unroll
            for (int h = 0; h < 2; ++h) {
                const int row = wm*16 + (lane >> 2) + h*8;
                const float m2inv = -2.0f * inv_s[row];
                #pragma unroll
                for (int nt = 0; nt < 8; ++nt) {
                    int code = n0 + wn*64 + nt*8 + (lane & 3)*2;
                    float s0 = fmaf(m2inv, acc[nt][h*2+0], __ldg(&g_cnorm[code]));
                    float s1 = fmaf(m2inv, acc[nt][h*2+1], __ldg(&g_cnorm[code+1]));
                    if (s0 < bs1[h]) { bs2[h]=bs1[h]; bi2[h]=bi1[h]; bs1[h]=s0; bi1[h]=code; }
                    else if (s0 < bs2[h]) { bs2[h]=s0; bi2[h]=code; }
                    if (s1 < bs1[h]) { bs2[h]=bs1[h]; bi2[h]=bi1[h]; bs1[h]=s1; bi1[h]=code+1; }
                    else if (s1 < bs2[h]) { bs2[h]=s1; bi2[h]=code+1; }
                }
            }
            #pragma unroll
            for (int b = 0; b < 8; ++b)
                #pragma unroll
                for (int e = 0; e < 4; ++e) acc[b][e] = 0.f;
        }
    }

    // ---- candidate reduction: 8 slices x top-2 = 16 candidates/row ----
    __syncthreads();
    #pragma unroll
    for (int h = 0; h < 2; ++h) {
        const int row = wm*16 + (lane >> 2) + h*8;
        const int cb = (wn*4 + (lane & 3))*2;
        red_s[row*16 + cb]     = bs1[h]; red_i[row*16 + cb]     = bi1[h];
        red_s[row*16 + cb + 1] = bs2[h]; red_i[row*16 + cb + 1] = bi2[h];
    }
    __syncthreads();

    if (tid < M_TILE) {
        float s1 = 3.4e38f, s2 = s1, s3 = s1, s4 = s1;
        int i1 = 0, i2 = 0, i3 = 0, i4 = 0;
        #pragma unroll
        for (int c = 0; c < 16; ++c) {
            float s = red_s[tid*16 + c]; int ii = red_i[tid*16 + c];
            if (s < s1 || (s == s1 && ii < i1)) { s4=s3;i4=i3; s3=s2;i3=i2; s2=s1;i2=i1; s1=s;i1=ii; }
            else if (s < s2 || (s == s2 && ii < i2)) { s4=s3;i4=i3; s3=s2;i3=i2; s2=s;i2=ii; }
            else if (s < s3 || (s == s3 && ii < i3)) { s4=s3;i4=i3; s3=s;i3=ii; }
            else if (s < s4 || (s == s4 && ii < i4)) { s4=s;i4=ii; }
        }
        idx4_s[tid*4+0] = i1; idx4_s[tid*4+1] = i2;
        idx4_s[tid*4+2] = i3; idx4_s[tid*4+3] = i4;
        flag_s[tid] = (s2 - s1 < 3e-3f) ? 1 : 0;
        provS[tid] = s1; provI[tid] = i1;
    }
    __syncthreads();

    // ---- quad-cooperative exact-fp32 rescue: 4 same-warp threads per row ----
    {
        const int row = tid >> 2, part = tid & 3;
        const int flg = flag_s[row];
        float p0 = 0.f, p1 = 0.f, p2 = 0.f, p3 = 0.f;
        int ic0 = idx4_s[row*4+0], ic1 = idx4_s[row*4+1];
        int ic2 = idx4_s[row*4+2], ic3 = idx4_s[row*4+3];
        if (flg) {
            const float* xr = x + (size_t)n*D*T + t0 + row;
            const float* cb0 = codebook + (size_t)ic0*D;
            const float* cb1 = codebook + (size_t)ic1*D;
            const float* cb2 = codebook + (size_t)ic2*D;
            const float* cb3 = codebook + (size_t)ic3*D;
            const int dlo = part*128;
            #pragma unroll 4
            for (int d = dlo; d < dlo + 128; ++d) {
                float xv = xr[(size_t)d*T];
                p0 = fmaf(xv, cb0[d], p0);
                p1 = fmaf(xv, cb1[d], p1);
                p2 = fmaf(xv, cb2[d], p2);
                p3 = fmaf(xv, cb3[d], p3);
            }
        }
        p0 += __shfl_xor_sync(0xffffffffu, p0, 1);
        p1 += __shfl_xor_sync(0xffffffffu, p1, 1);
        p2 += __shfl_xor_sync(0xffffffffu, p2, 1);
        p3 += __shfl_xor_sync(0xffffffffu, p3, 1);
        p0 += __shfl_xor_sync(0xffffffffu, p0, 2);
        p1 += __shfl_xor_sync(0xffffffffu, p1, 2);
        p2 += __shfl_xor_sync(0xffffffffu, p2, 2);
        p3 += __shfl_xor_sync(0xffffffffu, p3, 2);
        if (part == 0) {
            float bestS = provS[row]; int bestI = provI[row];
            if (flg) {
                const float inv = inv_s[row];
                float e0 = fmaf(-2.0f*inv, p0, __ldg(&g_cnorm[ic0]));
                float e1 = fmaf(-2.0f*inv, p1, __ldg(&g_cnorm[ic1]));
                float e2 = fmaf(-2.0f*inv, p2, __ldg(&g_cnorm[ic2]));
                float e3 = fmaf(-2.0f*inv, p3, __ldg(&g_cnorm[ic3]));
                bestS = e0; bestI = ic0;
                if (e1 < bestS || (e1 == bestS && ic1 < bestI)) { bestS = e1; bestI = ic1; }
                if (e2 < bestS || (e2 == bestS && ic2 < bestI)) { bestS = e2; bestI = ic2; }
                if (e3 < bestS || (e3 == bestS && ic3 < bestI)) { bestS = e3; bestI = ic3; }
            }
            idx_s[row] = bestI;
            cm_s[row] = fmaf(sq_s[row]*inv_s[row], inv_s[row], bestS);
            atomicAdd(&g_hist[bestI], 1);
        }
    }
    __syncthreads();
    if (tid == 0) {
        float s = 0.f;
        for (int i = 0; i < M_TILE; ++i) s += cm_s[i];
        g_blockCommit[blk] = s;
    }

    // ---- fused output: gather + register transpose + coalesced write ----
    {
        const int mq = tid & 15;      // t-quad
        const int dg = tid >> 4;      // d-group of 4
        int r0i = idx_s[4*mq + 0], r1i = idx_s[4*mq + 1];
        int r2i = idx_s[4*mq + 2], r3i = idx_s[4*mq + 3];
        #pragma unroll
        for (int dt = 0; dt < 8; ++dt) {
            const int d0 = dt*64 + dg*4;
            float4 a = *reinterpret_cast<const float4*>(codebook + (size_t)r0i*D + d0);
            float4 b = *reinterpret_cast<const float4*>(codebook + (size_t)r1i*D + d0);
            float4 cc = *reinterpret_cast<const float4*>(codebook + (size_t)r2i*D + d0);
            float4 dd = *reinterpret_cast<const float4*>(codebook + (size_t)r3i*D + d0);
            float* ob = out + ((size_t)n*D + d0)*T + t0 + 4*mq;
            *reinterpret_cast<float4*>(ob)              = make_float4(a.x, b.x, cc.x, dd.x);
            *reinterpret_cast<float4*>(ob + T)          = make_float4(a.y, b.y, cc.y, dd.y);
            *reinterpret_cast<float4*>(ob + 2*(size_t)T)= make_float4(a.z, b.z, cc.z, dd.z);
            *reinterpret_cast<float4*>(ob + 3*(size_t)T)= make_float4(a.w, b.w, cc.w, dd.w);
        }
    }
}

// ---------------- finalize: perplexity + commit mean ----------------
__global__ void finalize_kernel(float* __restrict__ out) {
    __shared__ double sbuf[512];
    int t = threadIdx.x;
    float prob = (float)g_hist[t] / 65536.0f;
    sbuf[t] = (double)(prob * logf(prob + 1e-7f));
    __syncthreads();
    for (int s = 256; s > 0; s >>= 1) { if (t < s) sbuf[t] += sbuf[t+s]; __syncthreads(); }
    double psum = sbuf[0];
    __syncthreads();
    double c = 0.0;
    for (int i = t; i < CTAS; i += 512) c += (double)g_blockCommit[i];
    sbuf[t] = c;
    __syncthreads();
    for (int s = 256; s > 0; s >>= 1) { if (t < s) sbuf[t] += sbuf[t+s]; __syncthreads(); }
    if (t == 0) {
        out[(size_t)R*D]     = (float)(sbuf[0] / ((double)R * (double)D));
        out[(size_t)R*D + 1] = expf((float)(-psum));
    }
}

// ---------------- launch ----------------
extern "C" void kernel_launch(void* const* d_in, const int* in_sizes, int n_in,
                              void* d_out, int out_size) {
    const float* x        = (const float*)d_in[0];
    const float* codebook = (const float*)d_in[1];
    float* out = (float*)d_out;

    cudaFuncSetAttribute(vq_main, cudaFuncAttributeMaxDynamicSharedMemorySize, SMEM_TOTAL);

    prep_cb<<<NB, D>>>(codebook);
    vq_main<<<CTAS, 256, SMEM_TOTAL>>>(x, codebook, out);
    finalize_kernel<<<1, 512>>>(out);
}